// round 12
// baseline (speedup 1.0000x reference)
#include <cuda_runtime.h>
#include <cuda_bf16.h>

#define NG 128
#define NT 512
#define SP 28          // padded row stride (floats) = 112B, 16B-aligned
#define NTH 704        // 576 T + 96 H + 32 S

__device__ __forceinline__ void bsync(int id, int cnt) {
    asm volatile("bar.sync %0, %1;" :: "r"(id), "r"(cnt) : "memory");
}
__device__ __forceinline__ void barrv(int id, int cnt) {
    asm volatile("bar.arrive %0, %1;" :: "r"(id), "r"(cnt) : "memory");
}

// 24-dot with 4 independent FMA chains + tree reduce.
__device__ __forceinline__ float dot24(const float4* __restrict__ a, const float4* __restrict__ b) {
    float ax = 0.f, ay = 0.f, az = 0.f, aw = 0.f;
#pragma unroll
    for (int c = 0; c < 6; ++c) {
        float4 x = a[c], y = b[c];
        ax = __fmaf_rn(x.x, y.x, ax);
        ay = __fmaf_rn(x.y, y.y, ay);
        az = __fmaf_rn(x.z, y.z, az);
        aw = __fmaf_rn(x.w, y.w, aw);
    }
    return (ax + ay) + (az + aw);
}
__device__ __forceinline__ float dot24r(const float4 fr[6], const float4* __restrict__ b) {
    float ax = 0.f, ay = 0.f, az = 0.f, aw = 0.f;
#pragma unroll
    for (int c = 0; c < 6; ++c) {
        float4 y = b[c];
        ax = __fmaf_rn(fr[c].x, y.x, ax);
        ay = __fmaf_rn(fr[c].y, y.y, ay);
        az = __fmaf_rn(fr[c].z, y.z, az);
        aw = __fmaf_rn(fr[c].w, y.w, aw);
    }
    return (ax + ay) + (az + aw);
}

// 4x4 determinant, straight-line, independent chains (no shuffles).
__device__ __forceinline__ float det4(const float* m) {
    float s0 = m[10]*m[15] - m[11]*m[14];
    float s1 = m[9] *m[15] - m[11]*m[13];
    float s2 = m[9] *m[14] - m[10]*m[13];
    float s3 = m[8] *m[15] - m[11]*m[12];
    float s4 = m[8] *m[14] - m[10]*m[12];
    float s5 = m[8] *m[13] - m[9] *m[12];
    float c0 = m[5]*s0 - m[6]*s1 + m[7]*s2;
    float c1 = m[4]*s0 - m[6]*s3 + m[7]*s4;
    float c2 = m[4]*s1 - m[5]*s3 + m[7]*s5;
    float c3 = m[4]*s2 - m[5]*s4 + m[6]*s5;
    return m[0]*c0 - m[1]*c1 + m[2]*c2 - m[3]*c3;
}

__global__ __launch_bounds__(NTH, 1)
void kalman_kernel(const float* __restrict__ y_in,   // (G,T,4)
                   const float* __restrict__ F_in,   // (G,T,24,24)
                   const float* __restrict__ Q_in,   // (G,T,24,24)
                   const float* __restrict__ H_in,   // (G,T,4,24)
                   const float* __restrict__ R_in,   // (G,T,4,4)
                   const float* __restrict__ m0_in,  // (G,24)
                   const float* __restrict__ P0_in,  // (G,24,24)
                   float* __restrict__ out)
{
    __shared__ __align__(16) float P  [24*SP];
    __shared__ __align__(16) float G1 [2][24*SP];  // double-buffered
    __shared__ __align__(16) float Fs [2][24*SP];  // double-buffered
    __shared__ __align__(16) float Hs [2][4*SP];   // double-buffered
    __shared__ __align__(16) float HPs[4*SP];
    __shared__ __align__(16) float Bm [96];        // (F P H^T), row i -> Bm[i*4+q]
    __shared__ __align__(16) float Cm [96];        // Bm @ Sinv, row i -> Cm[i*4+q]
    __shared__ __align__(16) float Sinv[16];
    __shared__ __align__(16) float mvec[24];
    __shared__ __align__(16) float Fm [24];
    __shared__ __align__(16) float Sg[16];
    __shared__ float Hm[4];
    __shared__ float ys[2][4];

    const int tid = threadIdx.x;
    const int g   = blockIdx.x;
    const size_t baseT = (size_t)g * NT;
    float* outMean = out;
    float* outCov  = out + (size_t)NG * NT * 4;

    const int w = tid >> 5, l = tid & 31;

    if (tid < 576) {
        // =================== T role: covariance propagation ===================
        const int ti    = (w % 3) * 8 + (l & 7);
        const int tj    = (w / 3) * 4 + (l >> 3);
        const int blk   = w / 3;               // owns P rows [4blk, 4blk+4)
        const int prodc = w % 3;               // G1-row producer class (rows 8c..8c+7)
        const int consc = blk >> 1;            // G1-row consumer class
        const int li    = tid / 24, lj = tid % 24;

        P [li*SP+lj]     = P0_in[(size_t)g*576 + tid];
        Fs[0][li*SP+lj]  = F_in[baseT*576 + tid];
        float qCur       = Q_in[baseT*576 + tj*24 + ti];
        if (tid < 24) mvec[tid] = m0_in[g*24 + tid];
        bsync(1, 704);   // prologue (id1 reused: later uses have disjoint participants)

        const float* pF = F_in + baseT*576 + 576 + tid;
        const float* pQ = Q_in + baseT*576 + 576 + tj*24 + ti;
        float4 frow[6];

        for (int t = 0; t < NT-1; ++t) {
            const int cur = t & 1, nxt = cur ^ 1;
            float fN = *pF; pF += 576;
            float qN = *pQ; pQ += 576;

            // ---- A: G1[ti][tj] = F row ti . P row tj  (P symmetric) ----
            const float4* fr = (const float4*)&Fs[cur][ti*SP];
#pragma unroll
            for (int c = 0; c < 6; ++c) frow[c] = fr[c];
            G1[cur][ti*SP+tj] = dot24r(frow, (const float4*)&P[tj*SP]);
            if (prodc != consc) barrv(1 + prodc, 320);
            bsync(1 + consc, 320);

            // ---- B: FPF[tj][ti] = G1 row tj . F row ti + Q[tj][ti]; stash F ----
            float fpf = qCur + dot24r(frow, (const float4*)&G1[cur][tj*SP]);
            Fs[nxt][li*SP+lj] = fN;
            qCur = qN;
            bsync(6, 704);                 // wait Bm (H) + Cm (S)

            // ---- D: P[tj][ti] = fpf - C_ti . b_tj ----
            float4 ci = *(const float4*)&Cm[ti*4];
            float4 bj = *(const float4*)&Bm[tj*4];
            float corr = ci.x*bj.x + ci.y*bj.y + ci.z*bj.z + ci.w*bj.w;
            P[tj*SP+ti] = fpf - corr;

            barrv(7, 672);                 // H may read new P
            bsync(8 + blk, 96);            // own tj-block converges
        }
        // T not needed for the final step's outputs.
    } else if (tid < 672) {
        // =================== H role: HP = H P,  Bm = F (HP)^T ===================
        const int u = tid - 576, uq = u / 24, us = u % 24;

        Hs[0][uq*SP + us] = H_in[baseT*96 + u];
        bsync(1, 704);

        const float* pH = H_in + baseT*96 + 96 + u;

        for (int t = 0; t < NT-1; ++t) {
            const int cur = t & 1, nxt = cur ^ 1;
            float hN = *pH; pH += 96;

            HPs[uq*SP+us] = dot24((const float4*)&Hs[cur][uq*SP],
                                  (const float4*)&P[us*SP]);
            bsync(4, 128);                 // HP complete

            Bm[us*4 + uq] = dot24((const float4*)&Fs[cur][us*SP],
                                  (const float4*)&HPs[uq*SP]);
            Hs[nxt][uq*SP + us] = hN;
            barrv(5, 128);                 // S may read Bm + Hs stash done
            barrv(6, 704);                 // T may read Bm
            bsync(7, 672);                 // wait for new P before next HP
        }
        // epilogue t = NT-1: HP for the final Sigma
        {
            const int cur = (NT-1) & 1;
            HPs[uq*SP+us] = dot24((const float4*)&Hs[cur][uq*SP],
                                  (const float4*)&P[us*SP]);
            bsync(4, 128);
        }
    } else {
        // =================== S role: measurement, inverse, C, mean ===================
        const int sl = tid - 672;

        int ca=0, cb=0, r0=0, r1=0, r2=0, c0=0, c1=0, c2=0; float csign = 1.f;
        if (sl < 16) {
            ca = sl >> 2; cb = sl & 3;
            r0 = (ca==0)?1:0; r1 = (ca<=1)?2:1; r2 = (ca<=2)?3:2;
            c0 = (cb==0)?1:0; c1 = (cb<=1)?2:1; c2 = (cb<=2)?3:2;
            csign = ((ca+cb)&1) ? -1.f : 1.f;
        }

        float rCur = 0.f;
        if (sl < 16)              rCur = R_in[baseT*16 + sl];
        else if (sl < 20)         ys[0][sl-16] = y_in[baseT*4 + (sl-16)];
        bsync(1, 704);

        const float* pR = R_in + baseT*16 + 16 + sl;
        const float* pY = y_in + baseT*4  + 4  + (sl - 16);

        for (int t = 0; t < NT-1; ++t) {
            const int cur = t & 1, nxt = cur ^ 1;
            float rN = 0.f, yN = 0.f;
            if (sl < 16)      rN = *pR;
            else if (sl < 20) yN = *pY;
            pR += 16; pY += 4;

            // ---- A: Hm (-> mean out), Fm ----
            if (sl < 4) {
                float hm = dot24((const float4*)&Hs[cur][sl*SP], (const float4*)mvec);
                Hm[sl] = hm;
                outMean[(baseT+t)*4 + sl] = hm;
            } else if (sl < 28) {
                int i = sl - 4;
                Fm[i] = dot24((const float4*)&Fs[cur][i*SP], (const float4*)mvec);
            }
            bsync(4, 128);                 // HP ready

            // ---- B: Sm -> Sig out; Sinv (redundant det, no shuffles) ----
            if (sl < 16) {
                int q = sl >> 2, r = sl & 3;
                float sm = rCur + dot24((const float4*)&HPs[q*SP],
                                        (const float4*)&Hs[cur][r*SP]);
                Sg[sl] = sm;
                outCov[(baseT+t)*16 + sl] = sm;
            }
            __syncwarp();
            if (sl < 16) {
                const float* m = Sg;
                float m00=m[r0*4+c0], m01=m[r0*4+c1], m02=m[r0*4+c2];
                float m10=m[r1*4+c0], m11=m[r1*4+c1], m12=m[r1*4+c2];
                float m20=m[r2*4+c0], m21=m[r2*4+c1], m22=m[r2*4+c2];
                float d3 = m00*(m11*m22 - m12*m21)
                         - m01*(m10*m22 - m12*m20)
                         + m02*(m10*m21 - m11*m20);
                float det = det4(m);
                Sinv[cb*4+ca] = csign * d3 * (1.0f / det);
            }
            __syncwarp();                  // Sinv visible across warp
            bsync(5, 128);                 // Bm ready (and Hs[nxt] stashed)

            // ---- C = Bm @ Sinv (96 dot4s over 32 lanes) ----
#pragma unroll
            for (int k = 0; k < 3; ++k) {
                int e = sl + 32*k;
                int i = e >> 2, q = e & 3;
                Cm[e] = Bm[i*4+0]*Sinv[q]    + Bm[i*4+1]*Sinv[4+q]
                      + Bm[i*4+2]*Sinv[8+q]  + Bm[i*4+3]*Sinv[12+q];
            }
            __syncwarp();                  // Cm visible for mvec below
            bsync(6, 704);                 // publish Cm; order vs T's Fs stash

            // ---- tail (off critical path): m' = Fm + C (y - Hm) ----
            if (sl < 24) {
                float d0 = ys[cur][0] - Hm[0];
                float d1 = ys[cur][1] - Hm[1];
                float d2 = ys[cur][2] - Hm[2];
                float d3r = ys[cur][3] - Hm[3];
                mvec[sl] = Fm[sl] + Cm[sl*4+0]*d0 + Cm[sl*4+1]*d1
                         + Cm[sl*4+2]*d2 + Cm[sl*4+3]*d3r;
            }
            rCur = rN;
            if (sl >= 16 && sl < 20) ys[nxt][sl-16] = yN;
            __syncwarp();                  // mvec visible for next A
        }
        // epilogue t = NT-1: final mean + Sigma
        {
            const int cur = (NT-1) & 1;
            if (sl < 4) {
                float hm = dot24((const float4*)&Hs[cur][sl*SP], (const float4*)mvec);
                outMean[(baseT+NT-1)*4 + sl] = hm;
            }
            bsync(4, 128);
            if (sl < 16) {
                int q = sl >> 2, r = sl & 3;
                float sm = rCur + dot24((const float4*)&HPs[q*SP],
                                        (const float4*)&Hs[cur][r*SP]);
                outCov[(baseT+NT-1)*16 + sl] = sm;
            }
        }
    }
}

extern "C" void kernel_launch(void* const* d_in, const int* in_sizes, int n_in,
                              void* d_out, int out_size) {
    const float* y  = (const float*)d_in[0];
    const float* F  = (const float*)d_in[1];
    const float* Q  = (const float*)d_in[2];
    const float* H  = (const float*)d_in[3];
    const float* R  = (const float*)d_in[4];
    const float* m0 = (const float*)d_in[5];
    const float* P0 = (const float*)d_in[6];
    kalman_kernel<<<NG, NTH>>>(y, F, Q, H, R, m0, P0, (float*)d_out);
}

// round 14
// speedup vs baseline: 1.2084x; 1.2084x over previous
#include <cuda_runtime.h>
#include <cuda_bf16.h>

#define NG 128
#define NT 512
#define SP 28          // padded row stride (floats) = 112B, 16B-aligned
#define NTH 704        // 576 T + 96 H + 32 S

#define BSYNC(id,n)  asm volatile("bar.sync %0, %1;"   :: "n"(id), "r"(n) : "memory")
#define BARRV(id,n)  asm volatile("bar.arrive %0, %1;" :: "n"(id), "r"(n) : "memory")
#define BSYNCR(id,n) asm volatile("bar.sync %0, %1;"   :: "r"(id), "r"(n) : "memory")

// 24-dot with 4 independent FMA chains + tree reduce.
__device__ __forceinline__ float dot24(const float4* __restrict__ a, const float4* __restrict__ b) {
    float ax = 0.f, ay = 0.f, az = 0.f, aw = 0.f;
#pragma unroll
    for (int c = 0; c < 6; ++c) {
        float4 x = a[c], y = b[c];
        ax = __fmaf_rn(x.x, y.x, ax);
        ay = __fmaf_rn(x.y, y.y, ay);
        az = __fmaf_rn(x.z, y.z, az);
        aw = __fmaf_rn(x.w, y.w, aw);
    }
    return (ax + ay) + (az + aw);
}
__device__ __forceinline__ float dot24r(const float4 fr[6], const float4* __restrict__ b) {
    float ax = 0.f, ay = 0.f, az = 0.f, aw = 0.f;
#pragma unroll
    for (int c = 0; c < 6; ++c) {
        float4 y = b[c];
        ax = __fmaf_rn(fr[c].x, y.x, ax);
        ay = __fmaf_rn(fr[c].y, y.y, ay);
        az = __fmaf_rn(fr[c].z, y.z, az);
        aw = __fmaf_rn(fr[c].w, y.w, aw);
    }
    return (ax + ay) + (az + aw);
}

// 4x4 determinant, straight-line, independent chains (no shuffles).
__device__ __forceinline__ float det4(const float* m) {
    float s0 = m[10]*m[15] - m[11]*m[14];
    float s1 = m[9] *m[15] - m[11]*m[13];
    float s2 = m[9] *m[14] - m[10]*m[13];
    float s3 = m[8] *m[15] - m[11]*m[12];
    float s4 = m[8] *m[14] - m[10]*m[12];
    float s5 = m[8] *m[13] - m[9] *m[12];
    float c0 = m[5]*s0 - m[6]*s1 + m[7]*s2;
    float c1 = m[4]*s0 - m[6]*s3 + m[7]*s4;
    float c2 = m[4]*s1 - m[5]*s3 + m[7]*s5;
    float c3 = m[4]*s2 - m[5]*s4 + m[6]*s5;
    return m[0]*c0 - m[1]*c1 + m[2]*c2 - m[3]*c3;
}

__global__ __launch_bounds__(NTH, 1)
void kalman_kernel(const float* __restrict__ y_in,   // (G,T,4)
                   const float* __restrict__ F_in,   // (G,T,24,24)
                   const float* __restrict__ Q_in,   // (G,T,24,24)
                   const float* __restrict__ H_in,   // (G,T,4,24)
                   const float* __restrict__ R_in,   // (G,T,4,4)
                   const float* __restrict__ m0_in,  // (G,24)
                   const float* __restrict__ P0_in,  // (G,24,24)
                   float* __restrict__ out)
{
    __shared__ __align__(16) float P  [24*SP];
    __shared__ __align__(16) float G1 [2][24*SP];  // double-buffered
    __shared__ __align__(16) float Fs [2][24*SP];  // double-buffered
    __shared__ __align__(16) float Hs [2][4*SP];   // double-buffered
    __shared__ __align__(16) float HPs[4*SP];
    __shared__ __align__(16) float Bm [96];        // (F P H^T), row i -> Bm[i*4+q]
    __shared__ __align__(16) float Sinv[16];
    __shared__ __align__(16) float mvec[24];
    __shared__ __align__(16) float Fm [24];
    __shared__ __align__(16) float Sg[16];
    __shared__ float Hm[4];
    __shared__ float ys[2][4];
    __shared__ float v4[4];

    const int tid = threadIdx.x;
    const int g   = blockIdx.x;
    const size_t baseT = (size_t)g * NT;
    float* outMean = out;
    float* outCov  = out + (size_t)NG * NT * 4;

    const int w = tid >> 5, l = tid & 31;

    if (tid < 576) {
        // =================== T role: covariance propagation ===================
        const int ti  = (w % 3) * 8 + (l & 7);
        const int tj  = (w / 3) * 4 + (l >> 3);
        const int blk = w / 3;                     // owns P rows [4blk, 4blk+4)
        const int li  = tid / 24, lj = tid % 24;   // flat coalesced map
        const int bid = 8 + blk;

        P [li*SP+lj]     = P0_in[(size_t)g*576 + tid];
        Fs[0][li*SP+lj]  = F_in[baseT*576 + tid];
        float qCur       = Q_in[baseT*576 + tj*24 + ti];
        if (tid < 24) mvec[tid] = m0_in[g*24 + tid];
        // distance-2 prefetch registers: values for step t+1
        float fA = F_in[(baseT+1)*576 + tid];
        float qA = Q_in[(baseT+1)*576 + tj*24 + ti];
        BSYNC(0, 704);

        const float* pF2 = F_in + (baseT+2)*576 + tid;
        const float* pQ2 = Q_in + (baseT+2)*576 + tj*24 + ti;
        float4 frow[6];

        for (int t = 0; t < NT-1; ++t) {
            const int cur = t & 1, nxt = cur ^ 1;
            // issue loads for step t+2 (consumed next iteration)
            float fB = 0.f, qB = 0.f;
            if (t < NT-2) { fB = *pF2; qB = *pQ2; }
            pF2 += 576; pQ2 += 576;

            // ---- A: G1[ti][tj] = F row ti . P row tj  (P symmetric) ----
            const float4* fr = (const float4*)&Fs[cur][ti*SP];
#pragma unroll
            for (int c = 0; c < 6; ++c) frow[c] = fr[c];
            G1[cur][ti*SP+tj] = dot24r(frow, (const float4*)&P[tj*SP]);
            BSYNC(1, 576);

            // ---- B: FPF[tj][ti] = G1 row tj . F row ti + Q[tj][ti]; stash F(t+1) ----
            float fpf = qCur + dot24r(frow, (const float4*)&G1[cur][tj*SP]);
            Fs[nxt][li*SP+lj] = fA;        // loaded a full iteration ago
            BSYNC(3, 704);                 // wait Bm (H arrive) + Sinv (S sync)

            // ---- D: P[tj][ti] = fpf - b_i Sinv b_j^T ----
            float4 si0 = *(const float4*)&Sinv[0];
            float4 si1 = *(const float4*)&Sinv[4];
            float4 si2 = *(const float4*)&Sinv[8];
            float4 si3 = *(const float4*)&Sinv[12];
            float4 bi  = *(const float4*)&Bm[ti*4];
            float u0 = bi.x*si0.x + bi.y*si1.x + bi.z*si2.x + bi.w*si3.x;
            float u1 = bi.x*si0.y + bi.y*si1.y + bi.z*si2.y + bi.w*si3.y;
            float u2 = bi.x*si0.z + bi.y*si1.z + bi.z*si2.z + bi.w*si3.z;
            float u3 = bi.x*si0.w + bi.y*si1.w + bi.z*si2.w + bi.w*si3.w;
            float4 bj = *(const float4*)&Bm[tj*4];
            float corr = u0*bj.x + u1*bj.y + u2*bj.z + u3*bj.w;
            P[tj*SP+ti] = fpf - corr;

            // rotate prefetch registers
            qCur = qA; qA = qB; fA = fB;

            BARRV(7, 672);                 // let H see completed P
            BSYNCR(bid, 96);               // only our tj-block must converge
        }
        // T not needed for the final step's outputs.
    } else if (tid < 672) {
        // =================== H role: HP = H P,  Bm = F (HP)^T ===================
        const int u = tid - 576, uq = u / 24, us = u % 24;

        Hs[0][uq*SP + us] = H_in[baseT*96 + u];
        float hA = H_in[(baseT+1)*96 + u];     // value for step t+1
        BSYNC(0, 704);

        const float* pH2 = H_in + (baseT+2)*96 + u;

        for (int t = 0; t < NT-1; ++t) {
            const int cur = t & 1, nxt = cur ^ 1;
            float hB = 0.f;
            if (t < NT-2) hB = *pH2;
            pH2 += 96;

            HPs[uq*SP+us] = dot24((const float4*)&Hs[cur][uq*SP],
                                  (const float4*)&P[us*SP]);
            BSYNC(2, 128);

            Bm[us*4 + uq] = dot24((const float4*)&Fs[cur][us*SP],
                                  (const float4*)&HPs[uq*SP]);
            Hs[nxt][uq*SP + us] = hA;      // loaded a full iteration ago
            hA = hB;
            BARRV(4, 128);                 // S may read Bm
            BARRV(3, 704);                 // T may read Bm
            BSYNC(7, 672);                 // wait for new P before next HP
        }
        // epilogue t = NT-1: HP for the final Sigma
        {
            const int cur = (NT-1) & 1;
            HPs[uq*SP+us] = dot24((const float4*)&Hs[cur][uq*SP],
                                  (const float4*)&P[us*SP]);
            BSYNC(2, 128);
        }
    } else {
        // =================== S role: measurement, inverse, mean ===================
        const int sl = tid - 672;

        int ca=0, cb=0, r0=0, r1=0, r2=0, c0=0, c1=0, c2=0; float csign = 1.f;
        if (sl < 16) {
            ca = sl >> 2; cb = sl & 3;
            r0 = (ca==0)?1:0; r1 = (ca<=1)?2:1; r2 = (ca<=2)?3:2;
            c0 = (cb==0)?1:0; c1 = (cb<=1)?2:1; c2 = (cb<=2)?3:2;
            csign = ((ca+cb)&1) ? -1.f : 1.f;
        }

        float rCur = 0.f, rA = 0.f, yA = 0.f;
        if (sl < 16) {
            rCur = R_in[baseT*16 + sl];
            rA   = R_in[(baseT+1)*16 + sl];
        } else if (sl < 20) {
            ys[0][sl-16] = y_in[baseT*4 + (sl-16)];
            yA           = y_in[(baseT+1)*4 + (sl-16)];
        }
        BSYNC(0, 704);

        const float* pR2 = R_in + (baseT+2)*16 + sl;
        const float* pY2 = y_in + (baseT+2)*4  + (sl - 16);

        for (int t = 0; t < NT-1; ++t) {
            const int cur = t & 1, nxt = cur ^ 1;
            float rB = 0.f, yB = 0.f;
            if (t < NT-2) {
                if (sl < 16)      rB = *pR2;
                else if (sl < 20) yB = *pY2;
            }
            pR2 += 16; pY2 += 4;

            // ---- A: Hm (-> mean out), Fm ----
            if (sl < 4) {
                float hm = dot24((const float4*)&Hs[cur][sl*SP], (const float4*)mvec);
                Hm[sl] = hm;
                outMean[(baseT+t)*4 + sl] = hm;
            } else if (sl < 28) {
                int i = sl - 4;
                Fm[i] = dot24((const float4*)&Fs[cur][i*SP], (const float4*)mvec);
            }
            BSYNC(2, 128);

            // ---- B: Sm -> Sig out; Sinv (redundant det, no shuffles) ----
            if (sl < 16) {
                int q = sl >> 2, r = sl & 3;
                float sm = rCur + dot24((const float4*)&HPs[q*SP],
                                        (const float4*)&Hs[cur][r*SP]);
                Sg[sl] = sm;
                outCov[(baseT+t)*16 + sl] = sm;
            }
            __syncwarp();
            if (sl < 16) {
                const float* m = Sg;
                float m00=m[r0*4+c0], m01=m[r0*4+c1], m02=m[r0*4+c2];
                float m10=m[r1*4+c0], m11=m[r1*4+c1], m12=m[r1*4+c2];
                float m20=m[r2*4+c0], m21=m[r2*4+c1], m22=m[r2*4+c2];
                float d3 = m00*(m11*m22 - m12*m21)
                         - m01*(m10*m22 - m12*m20)
                         + m02*(m10*m21 - m11*m20);
                float det = det4(m);
                Sinv[cb*4+ca] = csign * d3 * (1.0f / det);
            }
            BSYNC(3, 704);                 // publish Sinv; also orders T's Fs stash
            BSYNC(4, 128);                 // wait Bm from H

            // ---- D (off critical path): v4, m' ----
            if (sl < 4) {
                const float* si = &Sinv[sl*4];
                const float* yb = ys[cur];
                v4[sl] = si[0]*(yb[0]-Hm[0]) + si[1]*(yb[1]-Hm[1])
                       + si[2]*(yb[2]-Hm[2]) + si[3]*(yb[3]-Hm[3]);
            }
            __syncwarp();
            if (sl < 24) {
                mvec[sl] = Fm[sl] + Bm[sl*4+0]*v4[0] + Bm[sl*4+1]*v4[1]
                         + Bm[sl*4+2]*v4[2] + Bm[sl*4+3]*v4[3];
            }
            rCur = rA; rA = rB;
            if (sl >= 16 && sl < 20) ys[nxt][sl-16] = yA;
            yA = yB;
            __syncwarp();                  // mvec visible to next A
        }
        // epilogue t = NT-1: final mean + Sigma
        {
            const int cur = (NT-1) & 1;
            if (sl < 4) {
                float hm = dot24((const float4*)&Hs[cur][sl*SP], (const float4*)mvec);
                outMean[(baseT+NT-1)*4 + sl] = hm;
            }
            BSYNC(2, 128);
            if (sl < 16) {
                int q = sl >> 2, r = sl & 3;
                float sm = rCur + dot24((const float4*)&HPs[q*SP],
                                        (const float4*)&Hs[cur][r*SP]);
                outCov[(baseT+NT-1)*16 + sl] = sm;
            }
        }
    }
}

extern "C" void kernel_launch(void* const* d_in, const int* in_sizes, int n_in,
                              void* d_out, int out_size) {
    const float* y  = (const float*)d_in[0];
    const float* F  = (const float*)d_in[1];
    const float* Q  = (const float*)d_in[2];
    const float* H  = (const float*)d_in[3];
    const float* R  = (const float*)d_in[4];
    const float* m0 = (const float*)d_in[5];
    const float* P0 = (const float*)d_in[6];
    kalman_kernel<<<NG, NTH>>>(y, F, Q, H, R, m0, P0, (float*)d_out);
}